// round 13
// baseline (speedup 1.0000x reference)
#include <cuda_runtime.h>
#include <cuda_fp16.h>
#include <cstdint>

// Problem constants
#define BSZ 2
#define SEQ 8192
#define FD  512
#define NH  8
#define HD  64
#define NB  64          // SEQ / 128
#define MROWS (BSZ*SEQ) // 16384
#define NTK  8          // k-tiles of 64 over FD

// Scratch (allocation-free rule -> __device__ globals). fp16 everywhere.
__device__ __half g_aq [(size_t)MROWS*FD];     // inputs_q  fp16
__device__ __half g_akv[(size_t)MROWS*FD];     // inputs_kv fp16
__device__ __half g_wq [(size_t)FD*FD];        // W transposed [n][k] fp16
__device__ __half g_wk [(size_t)FD*FD];
__device__ __half g_wv [(size_t)FD*FD];
__device__ __half g_wo [(size_t)FD*FD];
__device__ __half g_q[(size_t)BSZ*NH*SEQ*HD];  // [B,H,S,D]
__device__ __half g_k[(size_t)BSZ*NH*SEQ*HD];
__device__ __half g_v[(size_t)BSZ*NH*SEQ*HD];
__device__ __half g_o[(size_t)BSZ*SEQ*NH*HD];  // [B,S,H,D]

__device__ __forceinline__ unsigned smaddr(const void* p) {
    return (unsigned)__cvta_generic_to_shared(p);
}
__device__ __forceinline__ unsigned packh2(float lo, float hi) {
    unsigned r;
    asm("cvt.rn.f16x2.f32 %0, %1, %2;" : "=r"(r) : "f"(hi), "f"(lo));
    return r;
}
#define CP16(dst, src) asm volatile("cp.async.cg.shared.global [%0], [%1], 16;\n" :: "r"(dst), "l"(src))
#define CP_COMMIT()    asm volatile("cp.async.commit_group;\n")
#define CP_WAIT(n)     asm volatile("cp.async.wait_group %0;\n" :: "n"(n))

#define LDSM4(r0,r1,r2,r3,a) \
    asm volatile("ldmatrix.sync.aligned.m8n8.x4.shared.b16 {%0,%1,%2,%3}, [%4];" \
                 : "=r"(r0), "=r"(r1), "=r"(r2), "=r"(r3) : "r"(a))
#define LDSM4T(r0,r1,r2,r3,a) \
    asm volatile("ldmatrix.sync.aligned.m8n8.x4.trans.shared.b16 {%0,%1,%2,%3}, [%4];" \
                 : "=r"(r0), "=r"(r1), "=r"(r2), "=r"(r3) : "r"(a))
#define MMA16816(c, a0,a1,a2,a3, b0,b1) \
    asm volatile("mma.sync.aligned.m16n8k16.row.col.f32.f16.f16.f32 " \
                 "{%0,%1,%2,%3}, {%4,%5,%6,%7}, {%8,%9}, {%0,%1,%2,%3};" \
                 : "+f"((c)[0]), "+f"((c)[1]), "+f"((c)[2]), "+f"((c)[3]) \
                 : "r"(a0), "r"(a1), "r"(a2), "r"(a3), "r"(b0), "r"(b1))

// ---------------------------------------------------------------------------
// Kernel 0: fused preamble. blocks [0,1024): activations fp32->fp16.
// blocks [1024,2048): weight transpose+convert dst[n][k] = fp16(src[k][n]).
// ---------------------------------------------------------------------------
#define SEG_A 2097152u             // MROWS*FD/4
__global__ void pre_kernel(
    const float4* __restrict__ q, const float4* __restrict__ kv,
    const float* __restrict__ wq, const float* __restrict__ wk,
    const float* __restrict__ wv, const float* __restrict__ wo)
{
    __shared__ float t[32][33];
    const int tid = threadIdx.x;
    if (blockIdx.x < 1024) {
        for (unsigned i = blockIdx.x * 256 + tid; i < 2 * SEG_A; i += 1024 * 256) {
            const float4* src = (i < SEG_A) ? q : kv;
            uint2* dst = (i < SEG_A) ? (uint2*)g_aq : (uint2*)g_akv;
            unsigned off = (i < SEG_A) ? i : i - SEG_A;
            float4 v = src[off];
            dst[off] = make_uint2(packh2(v.x, v.y), packh2(v.z, v.w));
        }
    } else {
        const int bid = blockIdx.x - 1024;      // 0..1023
        const int z = bid >> 8;                 // weight index
        const int tt = bid & 255;
        const float* src = (z == 0) ? wq : (z == 1 ? wk : (z == 2 ? wv : wo));
        __half* dst      = (z == 0) ? g_wq : (z == 1 ? g_wk : (z == 2 ? g_wv : g_wo));
        const int bk = (tt & 15) * 32;
        const int bn = (tt >> 4) * 32;
        const int tx = tid & 31;
        const int ty = tid >> 5;                // 0..7
#pragma unroll
        for (int i = 0; i < 4; i++) {
            int k = ty + i * 8;
            t[k][tx] = src[(size_t)(bk + k) * FD + bn + tx];
        }
        __syncthreads();
#pragma unroll
        for (int i = 0; i < 4; i++) {
            int nn = ty + i * 8;
            dst[(size_t)(bn + nn) * FD + bk + tx] = __float2half_rn(t[tx][nn]);
        }
    }
}

// ---------------------------------------------------------------------------
// fp16 GEMM body: C 128x64 tile, BK=64, 256 threads (8 warps, 16x64 tiles).
// 3-stage / 2-ahead cp.async pipeline, ONE __syncthreads per k-tile.
// Smem per stage: A 16KB + B 8KB = 24KB; 3 stages = 72KB. 3 CTAs/SM.
// Per warp accum = 32 regs -> reg budget fits launch_bounds(256,3).
// ---------------------------------------------------------------------------
#define GST3 24576u
#define GAOF(s) ((s) * GST3)
#define GBOF(s) ((s) * GST3 + 16384u)
#define GEMM_SMEM 73728

__device__ __forceinline__ void gemm_issue16(
    const __half* __restrict__ A, const __half* __restrict__ Bt,
    int m0, int n0, int kt, int s, unsigned sbase)
{
    const int tid = threadIdx.x;
    const unsigned ab = sbase + GAOF(s);
    const unsigned bb = sbase + GBOF(s);
#pragma unroll
    for (int i = 0; i < 4; i++) {          // A: 1024 units (128 rows x 8)
        int u = i * 256 + tid;
        int row = u >> 3, un = u & 7;
        unsigned sw = (unsigned)(row * 128) + ((un * 16) ^ ((row & 7) << 4));
        CP16(ab + sw, A + (size_t)(m0 + row) * FD + kt * 64 + un * 8);
    }
#pragma unroll
    for (int i = 0; i < 2; i++) {          // B: 512 units (64 rows x 8)
        int u = i * 256 + tid;
        int row = u >> 3, un = u & 7;
        unsigned sw = (unsigned)(row * 128) + ((un * 16) ^ ((row & 7) << 4));
        CP16(bb + sw, Bt + (size_t)(n0 + row) * FD + kt * 64 + un * 8);
    }
    CP_COMMIT();
}

__device__ __forceinline__ void gemm16_body(
    const __half* __restrict__ A, const __half* __restrict__ Bt,
    int m0, int n0, float acc[8][4], char* smem)
{
    const int lane = threadIdx.x & 31;
    const int warp = threadIdx.x >> 5;
    const int wm = warp * 16;              // warp owns rows wm..wm+15, all 64 cols
    const unsigned sbase = smaddr(smem);
    const int l15 = lane & 15;
    const int hb16 = (lane & 16) ? 16 : 0;

    gemm_issue16(A, Bt, m0, n0, 0, 0, sbase);
    gemm_issue16(A, Bt, m0, n0, 1, 1, sbase);

    int s = 0, s2 = 2;   // s = compute stage (kt%3), s2 = stage for kt+2
    for (int kt = 0; kt < NTK; kt++) {
        if (kt + 1 < NTK) { CP_WAIT(1); }
        else              { CP_WAIT(0); }
        __syncthreads();   // also protects buffer s2 (read at kt-1) for refill

        if (kt + 2 < NTK)
            gemm_issue16(A, Bt, m0, n0, kt + 2, s2, sbase);

        const unsigned ab = sbase + GAOF(s);
        const unsigned bb = sbase + GBOF(s);

        // Preload all 4 A fragments (one m16 row group, 4 k-chunks).
        unsigned af[4][4];
        {
            int row = wm + l15;
            unsigned rbase = ab + row * 128;
            unsigned xr = (row & 7) << 4;
#pragma unroll
            for (int kk = 0; kk < 4; kk++)
                LDSM4(af[kk][0], af[kk][1], af[kk][2], af[kk][3],
                      rbase + ((unsigned)(kk * 32 + hb16) ^ xr));
        }
#pragma unroll
        for (int np = 0; np < 4; np++) {
            int row = np * 16 + l15;
            unsigned rbase = bb + row * 128;
            unsigned xr = (row & 7) << 4;
#pragma unroll
            for (int kk = 0; kk < 4; kk++) {
                unsigned r0, r1, r2, r3;
                LDSM4(r0, r1, r2, r3, rbase + ((unsigned)(kk * 32 + hb16) ^ xr));
                MMA16816(acc[2 * np],     af[kk][0], af[kk][1], af[kk][2], af[kk][3], r0, r2);
                MMA16816(acc[2 * np + 1], af[kk][0], af[kk][1], af[kk][2], af[kk][3], r1, r3);
            }
        }
        s  = (s  == 2) ? 0 : s  + 1;
        s2 = (s2 == 2) ? 0 : s2 + 1;
    }
}

// ---------------------------------------------------------------------------
// Kernel 1: QKV projection. grid = (8, 128, 3). 256 threads, 3 CTAs/SM.
// CTA tile 128 rows x 64 cols (one head column-block -> h fixed per CTA).
// ---------------------------------------------------------------------------
__global__ void __launch_bounds__(256, 3) qkv_kernel(
    const float* __restrict__ bq, const float* __restrict__ bk,
    const float* __restrict__ bv)
{
    extern __shared__ char smem[];
    const int z = blockIdx.z;
    const __half* A  = (z == 0) ? g_aq : g_akv;
    const __half* Bt = (z == 0) ? g_wq : (z == 1 ? g_wk : g_wv);
    const float* bias = (z == 0) ? bq : (z == 1 ? bk : bv);
    __half* O        = (z == 0) ? g_q : (z == 1 ? g_k : g_v);

    const int n0 = blockIdx.x * 64;
    const int m0 = blockIdx.y * 128;

    float acc[8][4];
#pragma unroll
    for (int ni = 0; ni < 8; ni++)
#pragma unroll
        for (int j = 0; j < 4; j++) acc[ni][j] = 0.f;

    gemm16_body(A, Bt, m0, n0, acc, smem);

    const int lane = threadIdx.x & 31;
    const int warp = threadIdx.x >> 5;
    const int wm = warp * 16;
    const int g   = lane >> 2;
    const int tig = lane & 3;
    const int h   = n0 >> 6;                   // fixed per CTA

#pragma unroll
    for (int ni = 0; ni < 8; ni++) {
        int col = n0 + ni * 8 + tig * 2;
        int db = col & 63;
        float2 bb = *(const float2*)(bias + col);
        int row0 = m0 + wm + g;
        int b = row0 >> 13;
        int s0 = row0 & (SEQ - 1);
        __half* base = O + ((size_t)(b * NH + h)) * (SEQ * HD) + db;
        *(unsigned*)(base + (size_t)s0 * HD) =
            packh2(acc[ni][0] + bb.x, acc[ni][1] + bb.y);
        *(unsigned*)(base + (size_t)(s0 + 8) * HD) =
            packh2(acc[ni][2] + bb.x, acc[ni][3] + bb.y);
    }
}

// ---------------------------------------------------------------------------
// Kernel 3: output projection. grid = (8, 128). 256 threads, 3 CTAs/SM.
// ---------------------------------------------------------------------------
__global__ void __launch_bounds__(256, 3) oproj_kernel(
    const float* __restrict__ bo, float* __restrict__ Out)
{
    extern __shared__ char smem[];
    const int n0 = blockIdx.x * 64;
    const int m0 = blockIdx.y * 128;

    float acc[8][4];
#pragma unroll
    for (int ni = 0; ni < 8; ni++)
#pragma unroll
        for (int j = 0; j < 4; j++) acc[ni][j] = 0.f;

    gemm16_body(g_o, g_wo, m0, n0, acc, smem);

    const int lane = threadIdx.x & 31;
    const int warp = threadIdx.x >> 5;
    const int wm = warp * 16;
    const int g   = lane >> 2;
    const int tig = lane & 3;

#pragma unroll
    for (int ni = 0; ni < 8; ni++) {
        int col = n0 + ni * 8 + tig * 2;
        float2 bb = *(const float2*)(bo + col);
        int row0 = m0 + wm + g;
        *(float2*)(Out + (size_t)row0 * FD + col) =
            make_float2(acc[ni][0] + bb.x, acc[ni][1] + bb.y);
        *(float2*)(Out + (size_t)(row0 + 8) * FD + col) =
            make_float2(acc[ni][2] + bb.x, acc[ni][3] + bb.y);
    }
}

// ---------------------------------------------------------------------------
// Kernel 2: banded local attention. grid = (NB, NH, BSZ). 256 threads.
// 3-buffer / 2-ahead K,V pipeline, ONE __syncthreads per chunk. (unchanged)
// Smem: Q 16KB @0; 3 stages x (K 8KB + V 8KB) @16384. Total 64KB.
// ---------------------------------------------------------------------------
#define QOFF 0u
#define KOFF(s) (16384u + (s) * 16384u)
#define VOFF(s) (16384u + (s) * 16384u + 8192u)
#define ATTN_SMEM 65536

__device__ __forceinline__ void attn_issue_chunk(
    const __half* gk, const __half* gv, size_t rb, int s, unsigned sbase)
{
    const int tid = threadIdx.x;
#pragma unroll
    for (int i = 0; i < 2; i++) {
        int u = i * 256 + tid;          // 512 units: 64 rows x 8
        int row = u >> 3, un = u & 7;
        unsigned sw = (unsigned)(row * 128) + ((un * 16) ^ ((row & 7) << 4));
        CP16(sbase + KOFF(s) + sw, gk + rb + (size_t)row * HD + un * 8);
        CP16(sbase + VOFF(s) + sw, gv + rb + (size_t)row * HD + un * 8);
    }
    CP_COMMIT();
}

__global__ void __launch_bounds__(256, 2) attn_kernel()
{
    extern __shared__ char smem[];
    const unsigned sbase = smaddr(smem);

    const int n = blockIdx.x, h = blockIdx.y, b = blockIdx.z;
    const int tid  = threadIdx.x;
    const int lane = tid & 31;
    const int warp = tid >> 5;
    const int g    = lane >> 2;
    const int tig  = lane & 3;
    const int l15  = lane & 15;
    const int hb16 = (lane & 16) ? 16 : 0;
    const size_t hb = ((size_t)(b * NH + h)) * SEQ;

    // Chunk list (kb*2+ch); only out-of-range key blocks are dropped. L is 4 or 6.
    int cl[6]; int L = 0;
#pragma unroll
    for (int kb = 0; kb < 3; kb++) {
        int kn = n - 1 + kb;
        if (kn < 0 || kn >= NB) continue;
#pragma unroll
        for (int ch = 0; ch < 2; ch++) cl[L++] = kb * 2 + ch;
    }

    // Stage Q [128 x 64halves] (group 0)
#pragma unroll
    for (int i = 0; i < 4; i++) {
        int u = i * 256 + tid;              // 1024 units
        int row = u >> 3, un = u & 7;
        unsigned sw = (unsigned)(row * 128) + ((un * 16) ^ ((row & 7) << 4));
        CP16(sbase + QOFF + sw, g_q + (hb + (size_t)(n * 128 + row)) * HD + un * 8);
    }
    CP_COMMIT();
    // Stage chunks 0 and 1 into bufs 0 and 1 (groups 1 and 2)
    {
        int c0 = cl[0];
        attn_issue_chunk(g_k, g_v,
            (hb + (size_t)((n - 1 + (c0 >> 1)) * 128 + (c0 & 1) * 64)) * HD, 0, sbase);
        int c1 = cl[1];
        attn_issue_chunk(g_k, g_v,
            (hb + (size_t)((n - 1 + (c1 >> 1)) * 128 + (c1 & 1) * 64)) * HD, 1, sbase);
    }

    // Q fragments (wait leaves <=2 groups pending -> Q group complete)
    CP_WAIT(2);
    __syncthreads();
    unsigned qf[4][4];
    {
        const int row = warp * 16 + l15;
        const unsigned rbase = sbase + QOFF + row * 128;
        const unsigned xr = (row & 7) << 4;
#pragma unroll
        for (int kk = 0; kk < 4; kk++)
            LDSM4(qf[kk][0], qf[kk][1], qf[kk][2], qf[kk][3],
                  rbase + ((unsigned)(kk * 32 + hb16) ^ xr));
    }

    float oacc[8][4];
#pragma unroll
    for (int nd = 0; nd < 8; nd++)
#pragma unroll
        for (int e = 0; e < 4; e++) oacc[nd][e] = 0.f;
    float lr0 = 0.f, lr1 = 0.f;

    const int wq0 = warp * 16;
    const int qi0 = wq0 + g;

    int s = 0, s2 = 2;   // s = compute stage (i%3), s2 = stage for chunk i+2
    for (int i = 0; i < L; i++) {
        if (i + 1 < L) { CP_WAIT(1); }
        else           { CP_WAIT(0); }
        __syncthreads();   // protects buffer s2 (read at chunk i-1) for refill

        if (i + 2 < L) {
            int c = cl[i + 2];
            attn_issue_chunk(g_k, g_v,
                (hb + (size_t)((n - 1 + (c >> 1)) * 128 + (c & 1) * 64)) * HD,
                s2, sbase);
        }

        const unsigned kbs = sbase + KOFF(s);
        const unsigned vbs = sbase + VOFF(s);
        const int c  = cl[i];
        const int kb = c >> 1;
        const int jb = (c & 1) * 64;        // key offset within key block

        // Per-warp chunk skip: does [jb, jb+64) intersect this warp's band?
        const bool dowork =
            (kb == 1) || (kb == 0 ? (jb + 63 >= wq0) : (jb <= wq0 + 14));

        if (dowork) {
            // S = Q K^T : per warp [16 x 64]
            float acc[8][4];
#pragma unroll
            for (int ni = 0; ni < 8; ni++)
#pragma unroll
                for (int e = 0; e < 4; e++) acc[ni][e] = 0.f;

#pragma unroll
            for (int kk = 0; kk < 4; kk++) {
                const int bcol = kk * 32 + hb16;
#pragma unroll
                for (int jp = 0; jp < 4; jp++) {
                    int row = jp * 16 + l15;
                    unsigned bd = kbs + row * 128 + ((unsigned)bcol ^ ((row & 7) << 4));
                    unsigned r0, r1, r2, r3;
                    LDSM4(r0, r1, r2, r3, bd);
                    MMA16816(acc[2 * jp],     qf[kk][0], qf[kk][1], qf[kk][2], qf[kk][3], r0, r2);
                    MMA16816(acc[2 * jp + 1], qf[kk][0], qf[kk][1], qf[kk][2], qf[kk][3], r1, r3);
                }
            }

            // mask + exp; accumulate row sums
#pragma unroll
            for (int ni = 0; ni < 8; ni++) {
                const int j0 = jb + ni * 8 + tig * 2;   // key-in-block
                const int j1 = j0 + 1;
                bool v0, v1, v2, v3;
                if (kb == 1)      { v0 = v1 = v2 = v3 = true; }
                else if (kb == 0) { v0 = j0 >= qi0; v1 = j1 >= qi0;
                                    v2 = j0 >= qi0 + 8; v3 = j1 >= qi0 + 8; }
                else              { v0 = j0 < qi0; v1 = j1 < qi0;
                                    v2 = j0 < qi0 + 8; v3 = j1 < qi0 + 8; }
                float p0 = v0 ? __expf(acc[ni][0] * 0.125f) : 0.f;
                float p1 = v1 ? __expf(acc[ni][1] * 0.125f) : 0.f;
                float p2 = v2 ? __expf(acc[ni][2] * 0.125f) : 0.f;
                float p3 = v3 ? __expf(acc[ni][3] * 0.125f) : 0.f;
                lr0 += p0 + p1;
                lr1 += p2 + p3;
                acc[ni][0] = p0; acc[ni][1] = p1; acc[ni][2] = p2; acc[ni][3] = p3;
            }

            // O += P V (A-frag = packed C-frag; V via ldmatrix.trans)
#pragma unroll
            for (int jk = 0; jk < 4; jk++) {
                unsigned a0 = packh2(acc[2 * jk][0],     acc[2 * jk][1]);
                unsigned a1 = packh2(acc[2 * jk][2],     acc[2 * jk][3]);
                unsigned a2 = packh2(acc[2 * jk + 1][0], acc[2 * jk + 1][1]);
                unsigned a3 = packh2(acc[2 * jk + 1][2], acc[2 * jk + 1][3]);
#pragma unroll
                for (int np = 0; np < 4; np++) {
                    int row = jk * 16 + l15;
                    unsigned bd = vbs + row * 128 +
                                  ((unsigned)(np * 32 + hb16) ^ ((row & 7) << 4));
                    unsigned r0, r1, r2, r3;
                    LDSM4T(r0, r1, r2, r3, bd);
                    MMA16816(oacc[2 * np],     a0, a1, a2, a3, r0, r1);
                    MMA16816(oacc[2 * np + 1], a0, a1, a2, a3, r2, r3);
                }
            }
        }
        s  = (s  == 2) ? 0 : s  + 1;
        s2 = (s2 == 2) ? 0 : s2 + 1;
    }

    // finalize: intra-quad row sums, scale, store fp16
    lr0 += __shfl_xor_sync(0xffffffffu, lr0, 1);
    lr0 += __shfl_xor_sync(0xffffffffu, lr0, 2);
    lr1 += __shfl_xor_sync(0xffffffffu, lr1, 1);
    lr1 += __shfl_xor_sync(0xffffffffu, lr1, 2);
    const float inv0 = 1.f / lr0;
    const float inv1 = 1.f / lr1;

    const int row0 = n * 128 + warp * 16 + g;
    __half* ob0 = g_o + (((size_t)b * SEQ + row0) * NH + h) * HD;
    __half* ob1 = g_o + (((size_t)b * SEQ + row0 + 8) * NH + h) * HD;
#pragma unroll
    for (int nd = 0; nd < 8; nd++) {
        int d = nd * 8 + tig * 2;
        *(unsigned*)(ob0 + d) = packh2(oacc[nd][0] * inv0, oacc[nd][1] * inv0);
        *(unsigned*)(ob1 + d) = packh2(oacc[nd][2] * inv1, oacc[nd][3] * inv1);
    }
}

// ---------------------------------------------------------------------------
extern "C" void kernel_launch(void* const* d_in, const int* in_sizes, int n_in,
                              void* d_out, int out_size)
{
    const float* inputs_q  = (const float*)d_in[0];
    const float* inputs_kv = (const float*)d_in[1];
    const float* Wq = (const float*)d_in[2];
    const float* bq = (const float*)d_in[3];
    const float* Wk = (const float*)d_in[4];
    const float* bk = (const float*)d_in[5];
    const float* Wv = (const float*)d_in[6];
    const float* bv = (const float*)d_in[7];
    const float* Wo = (const float*)d_in[8];
    const float* bo = (const float*)d_in[9];
    float* out = (float*)d_out;

    // Idempotent host-side calls, executed every invocation (no static state).
    cudaFuncSetAttribute(qkv_kernel,   cudaFuncAttributeMaxDynamicSharedMemorySize, GEMM_SMEM);
    cudaFuncSetAttribute(oproj_kernel, cudaFuncAttributeMaxDynamicSharedMemorySize, GEMM_SMEM);
    cudaFuncSetAttribute(attn_kernel,  cudaFuncAttributeMaxDynamicSharedMemorySize, ATTN_SMEM);

    pre_kernel<<<2048, 256>>>((const float4*)inputs_q, (const float4*)inputs_kv,
                              Wq, Wk, Wv, Wo);

    dim3 gq(FD / 64, MROWS / 128, 3);
    qkv_kernel<<<gq, 256, GEMM_SMEM>>>(bq, bk, bv);

    dim3 ga(NB, NH, BSZ);
    attn_kernel<<<ga, 256, ATTN_SMEM>>>();

    dim3 go(FD / 64, MROWS / 128, 1);
    oproj_kernel<<<go, 256, GEMM_SMEM>>>(bo, out);
}

// round 14
// speedup vs baseline: 1.0214x; 1.0214x over previous
#include <cuda_runtime.h>
#include <cuda_fp16.h>
#include <cstdint>

// Problem constants
#define BSZ 2
#define SEQ 8192
#define FD  512
#define NH  8
#define HD  64
#define NB  64          // SEQ / 128
#define MROWS (BSZ*SEQ) // 16384
#define NTK  8          // k-tiles of 64 over FD

// Scratch (allocation-free rule -> __device__ globals). fp16 everywhere.
__device__ __half g_aq [(size_t)MROWS*FD];     // inputs_q  fp16
__device__ __half g_akv[(size_t)MROWS*FD];     // inputs_kv fp16
__device__ __half g_wq [(size_t)FD*FD];        // W transposed [n][k] fp16
__device__ __half g_wk [(size_t)FD*FD];
__device__ __half g_wv [(size_t)FD*FD];
__device__ __half g_wo [(size_t)FD*FD];
__device__ __half g_q[(size_t)BSZ*NH*SEQ*HD];  // [B,H,S,D]
__device__ __half g_k[(size_t)BSZ*NH*SEQ*HD];
__device__ __half g_v[(size_t)BSZ*NH*SEQ*HD];
__device__ __half g_o[(size_t)BSZ*SEQ*NH*HD];  // [B,S,H,D]

__device__ __forceinline__ unsigned smaddr(const void* p) {
    return (unsigned)__cvta_generic_to_shared(p);
}
__device__ __forceinline__ unsigned packh2(float lo, float hi) {
    unsigned r;
    asm("cvt.rn.f16x2.f32 %0, %1, %2;" : "=r"(r) : "f"(hi), "f"(lo));
    return r;
}
#define CP16(dst, src) asm volatile("cp.async.cg.shared.global [%0], [%1], 16;\n" :: "r"(dst), "l"(src))
#define CP_COMMIT()    asm volatile("cp.async.commit_group;\n")
#define CP_WAIT(n)     asm volatile("cp.async.wait_group %0;\n" :: "n"(n))

#define LDSM4(r0,r1,r2,r3,a) \
    asm volatile("ldmatrix.sync.aligned.m8n8.x4.shared.b16 {%0,%1,%2,%3}, [%4];" \
                 : "=r"(r0), "=r"(r1), "=r"(r2), "=r"(r3) : "r"(a))
#define LDSM4T(r0,r1,r2,r3,a) \
    asm volatile("ldmatrix.sync.aligned.m8n8.x4.trans.shared.b16 {%0,%1,%2,%3}, [%4];" \
                 : "=r"(r0), "=r"(r1), "=r"(r2), "=r"(r3) : "r"(a))
#define MMA16816(c, a0,a1,a2,a3, b0,b1) \
    asm volatile("mma.sync.aligned.m16n8k16.row.col.f32.f16.f16.f32 " \
                 "{%0,%1,%2,%3}, {%4,%5,%6,%7}, {%8,%9}, {%0,%1,%2,%3};" \
                 : "+f"((c)[0]), "+f"((c)[1]), "+f"((c)[2]), "+f"((c)[3]) \
                 : "r"(a0), "r"(a1), "r"(a2), "r"(a3), "r"(b0), "r"(b1))

// ---------------------------------------------------------------------------
// Kernel 0: fused preamble. blocks [0,1024): activations fp32->fp16.
// blocks [1024,2048): weight transpose+convert dst[n][k] = fp16(src[k][n]).
// ---------------------------------------------------------------------------
#define SEG_A 2097152u             // MROWS*FD/4
__global__ void pre_kernel(
    const float4* __restrict__ q, const float4* __restrict__ kv,
    const float* __restrict__ wq, const float* __restrict__ wk,
    const float* __restrict__ wv, const float* __restrict__ wo)
{
    __shared__ float t[32][33];
    const int tid = threadIdx.x;
    if (blockIdx.x < 1024) {
        for (unsigned i = blockIdx.x * 256 + tid; i < 2 * SEG_A; i += 1024 * 256) {
            const float4* src = (i < SEG_A) ? q : kv;
            uint2* dst = (i < SEG_A) ? (uint2*)g_aq : (uint2*)g_akv;
            unsigned off = (i < SEG_A) ? i : i - SEG_A;
            float4 v = src[off];
            dst[off] = make_uint2(packh2(v.x, v.y), packh2(v.z, v.w));
        }
    } else {
        const int bid = blockIdx.x - 1024;      // 0..1023
        const int z = bid >> 8;                 // weight index
        const int tt = bid & 255;
        const float* src = (z == 0) ? wq : (z == 1 ? wk : (z == 2 ? wv : wo));
        __half* dst      = (z == 0) ? g_wq : (z == 1 ? g_wk : (z == 2 ? g_wv : g_wo));
        const int bk = (tt & 15) * 32;
        const int bn = (tt >> 4) * 32;
        const int tx = tid & 31;
        const int ty = tid >> 5;                // 0..7
#pragma unroll
        for (int i = 0; i < 4; i++) {
            int k = ty + i * 8;
            t[k][tx] = src[(size_t)(bk + k) * FD + bn + tx];
        }
        __syncthreads();
#pragma unroll
        for (int i = 0; i < 4; i++) {
            int nn = ty + i * 8;
            dst[(size_t)(bn + nn) * FD + bk + tx] = __float2half_rn(t[tx][nn]);
        }
    }
}

// ---------------------------------------------------------------------------
// fp16 GEMM body: C 128x64 tile, BK=64, 128 threads (4 warps, 32x64 tiles).
// 2-stage cp.async pipeline, 48KB smem/CTA -> 4 CTAs/SM (fine-grained
// barrier domains: each sync stalls only 4 warps).
// ---------------------------------------------------------------------------
#define G2ST 24576u
#define GAOF(s) ((s) * G2ST)
#define GBOF(s) ((s) * G2ST + 16384u)
#define GEMM_SMEM 49152

__device__ __forceinline__ void gemm_issue16(
    const __half* __restrict__ A, const __half* __restrict__ Bt,
    int m0, int n0, int kt, int s, unsigned sbase)
{
    const int tid = threadIdx.x;
    const unsigned ab = sbase + GAOF(s);
    const unsigned bb = sbase + GBOF(s);
#pragma unroll
    for (int i = 0; i < 8; i++) {          // A: 1024 units (128 rows x 8)
        int u = i * 128 + tid;
        int row = u >> 3, un = u & 7;
        unsigned sw = (unsigned)(row * 128) + ((un * 16) ^ ((row & 7) << 4));
        CP16(ab + sw, A + (size_t)(m0 + row) * FD + kt * 64 + un * 8);
    }
#pragma unroll
    for (int i = 0; i < 4; i++) {          // B: 512 units (64 rows x 8)
        int u = i * 128 + tid;
        int row = u >> 3, un = u & 7;
        unsigned sw = (unsigned)(row * 128) + ((un * 16) ^ ((row & 7) << 4));
        CP16(bb + sw, Bt + (size_t)(n0 + row) * FD + kt * 64 + un * 8);
    }
    CP_COMMIT();
}

__device__ __forceinline__ void gemm16_body(
    const __half* __restrict__ A, const __half* __restrict__ Bt,
    int m0, int n0, float acc[2][8][4], char* smem)
{
    const int lane = threadIdx.x & 31;
    const int warp = threadIdx.x >> 5;     // 0..3
    const int wm = warp * 32;              // warp owns rows wm..wm+31, all 64 cols
    const unsigned sbase = smaddr(smem);
    const int l15 = lane & 15;
    const int hb16 = (lane & 16) ? 16 : 0;

    gemm_issue16(A, Bt, m0, n0, 0, 0, sbase);
    gemm_issue16(A, Bt, m0, n0, 1, 1, sbase);

    for (int kt = 0; kt < NTK; kt++) {
        const int buf = kt & 1;
        if (kt + 2 < NTK) { CP_WAIT(1); }
        else              { CP_WAIT(0); }
        __syncthreads();

        const unsigned ab = sbase + GAOF(buf);
        const unsigned bb = sbase + GBOF(buf);
#pragma unroll
        for (int kk = 0; kk < 4; kk++) {
            const int bcol = kk * 32 + hb16;
            unsigned af[2][4];
#pragma unroll
            for (int mi = 0; mi < 2; mi++) {
                int row = wm + mi * 16 + l15;
                unsigned ad = ab + row * 128 + (bcol ^ ((row & 7) << 4));
                LDSM4(af[mi][0], af[mi][1], af[mi][2], af[mi][3], ad);
            }
#pragma unroll
            for (int np = 0; np < 4; np++) {
                int row = np * 16 + l15;
                unsigned bd = bb + row * 128 + (bcol ^ ((row & 7) << 4));
                unsigned r0, r1, r2, r3;
                LDSM4(r0, r1, r2, r3, bd);
#pragma unroll
                for (int mi = 0; mi < 2; mi++) {
                    MMA16816(acc[mi][2 * np],     af[mi][0], af[mi][1], af[mi][2], af[mi][3], r0, r2);
                    MMA16816(acc[mi][2 * np + 1], af[mi][0], af[mi][1], af[mi][2], af[mi][3], r1, r3);
                }
            }
        }
        __syncthreads();
        if (kt + 2 < NTK)
            gemm_issue16(A, Bt, m0, n0, kt + 2, buf, sbase);
    }
}

// ---------------------------------------------------------------------------
// Kernel 1: QKV projection. grid = (8, 128, 3). 128 threads, 4 CTAs/SM.
// CTA tile 128 rows x 64 cols (one head per CTA column block).
// ---------------------------------------------------------------------------
__global__ void __launch_bounds__(128, 4) qkv_kernel(
    const float* __restrict__ bq, const float* __restrict__ bk,
    const float* __restrict__ bv)
{
    extern __shared__ char smem[];
    const int z = blockIdx.z;
    const __half* A  = (z == 0) ? g_aq : g_akv;
    const __half* Bt = (z == 0) ? g_wq : (z == 1 ? g_wk : g_wv);
    const float* bias = (z == 0) ? bq : (z == 1 ? bk : bv);
    __half* O        = (z == 0) ? g_q : (z == 1 ? g_k : g_v);

    const int n0 = blockIdx.x * 64;
    const int m0 = blockIdx.y * 128;

    float acc[2][8][4];
#pragma unroll
    for (int mi = 0; mi < 2; mi++)
#pragma unroll
        for (int ni = 0; ni < 8; ni++)
#pragma unroll
            for (int j = 0; j < 4; j++) acc[mi][ni][j] = 0.f;

    gemm16_body(A, Bt, m0, n0, acc, smem);

    const int lane = threadIdx.x & 31;
    const int warp = threadIdx.x >> 5;
    const int wm = warp * 32;
    const int g   = lane >> 2;
    const int tig = lane & 3;
    const int h   = n0 >> 6;                   // fixed per CTA

#pragma unroll
    for (int mi = 0; mi < 2; mi++) {
#pragma unroll
        for (int ni = 0; ni < 8; ni++) {
            int col = n0 + ni * 8 + tig * 2;
            int db = col & 63;
            float2 bb = *(const float2*)(bias + col);
            int row0 = m0 + wm + mi * 16 + g;
            int b = row0 >> 13;
            int s0 = row0 & (SEQ - 1);
            __half* base = O + ((size_t)(b * NH + h)) * (SEQ * HD) + db;
            *(unsigned*)(base + (size_t)s0 * HD) =
                packh2(acc[mi][ni][0] + bb.x, acc[mi][ni][1] + bb.y);
            *(unsigned*)(base + (size_t)(s0 + 8) * HD) =
                packh2(acc[mi][ni][2] + bb.x, acc[mi][ni][3] + bb.y);
        }
    }
}

// ---------------------------------------------------------------------------
// Kernel 3: output projection. grid = (8, 128). 128 threads, 4 CTAs/SM.
// ---------------------------------------------------------------------------
__global__ void __launch_bounds__(128, 4) oproj_kernel(
    const float* __restrict__ bo, float* __restrict__ Out)
{
    extern __shared__ char smem[];
    const int n0 = blockIdx.x * 64;
    const int m0 = blockIdx.y * 128;

    float acc[2][8][4];
#pragma unroll
    for (int mi = 0; mi < 2; mi++)
#pragma unroll
        for (int ni = 0; ni < 8; ni++)
#pragma unroll
            for (int j = 0; j < 4; j++) acc[mi][ni][j] = 0.f;

    gemm16_body(g_o, g_wo, m0, n0, acc, smem);

    const int lane = threadIdx.x & 31;
    const int warp = threadIdx.x >> 5;
    const int wm = warp * 32;
    const int g   = lane >> 2;
    const int tig = lane & 3;

#pragma unroll
    for (int mi = 0; mi < 2; mi++) {
#pragma unroll
        for (int ni = 0; ni < 8; ni++) {
            int col = n0 + ni * 8 + tig * 2;
            float2 bb = *(const float2*)(bo + col);
            int row0 = m0 + wm + mi * 16 + g;
            *(float2*)(Out + (size_t)row0 * FD + col) =
                make_float2(acc[mi][ni][0] + bb.x, acc[mi][ni][1] + bb.y);
            *(float2*)(Out + (size_t)(row0 + 8) * FD + col) =
                make_float2(acc[mi][ni][2] + bb.x, acc[mi][ni][3] + bb.y);
        }
    }
}

// ---------------------------------------------------------------------------
// Kernel 2: banded local attention. grid = (NB, NH, BSZ). 256 threads.
// 3-buffer / 2-ahead K,V pipeline, ONE __syncthreads per chunk.
// NEW: fragment-level band skip — per-warp, per-16-key-block predicates
// skip QK (jp) and PV (jk) blocks entirely outside the warp's band.
// The mask/exp loop still runs for all ni, so masked lanes always get p=0.
// Smem: Q 16KB @0; 3 stages x (K 8KB + V 8KB) @16384. Total 64KB.
// ---------------------------------------------------------------------------
#define QOFF 0u
#define KOFF(s) (16384u + (s) * 16384u)
#define VOFF(s) (16384u + (s) * 16384u + 8192u)
#define ATTN_SMEM 65536

__device__ __forceinline__ void attn_issue_chunk(
    const __half* gk, const __half* gv, size_t rb, int s, unsigned sbase)
{
    const int tid = threadIdx.x;
#pragma unroll
    for (int i = 0; i < 2; i++) {
        int u = i * 256 + tid;          // 512 units: 64 rows x 8
        int row = u >> 3, un = u & 7;
        unsigned sw = (unsigned)(row * 128) + ((un * 16) ^ ((row & 7) << 4));
        CP16(sbase + KOFF(s) + sw, gk + rb + (size_t)row * HD + un * 8);
        CP16(sbase + VOFF(s) + sw, gv + rb + (size_t)row * HD + un * 8);
    }
    CP_COMMIT();
}

__global__ void __launch_bounds__(256, 2) attn_kernel()
{
    extern __shared__ char smem[];
    const unsigned sbase = smaddr(smem);

    const int n = blockIdx.x, h = blockIdx.y, b = blockIdx.z;
    const int tid  = threadIdx.x;
    const int lane = tid & 31;
    const int warp = tid >> 5;
    const int g    = lane >> 2;
    const int tig  = lane & 3;
    const int l15  = lane & 15;
    const int hb16 = (lane & 16) ? 16 : 0;
    const size_t hb = ((size_t)(b * NH + h)) * SEQ;

    // Chunk list (kb*2+ch); only out-of-range key blocks are dropped. L is 4 or 6.
    int cl[6]; int L = 0;
#pragma unroll
    for (int kb = 0; kb < 3; kb++) {
        int kn = n - 1 + kb;
        if (kn < 0 || kn >= NB) continue;
#pragma unroll
        for (int ch = 0; ch < 2; ch++) cl[L++] = kb * 2 + ch;
    }

    // Stage Q [128 x 64halves] (group 0)
#pragma unroll
    for (int i = 0; i < 4; i++) {
        int u = i * 256 + tid;              // 1024 units
        int row = u >> 3, un = u & 7;
        unsigned sw = (unsigned)(row * 128) + ((un * 16) ^ ((row & 7) << 4));
        CP16(sbase + QOFF + sw, g_q + (hb + (size_t)(n * 128 + row)) * HD + un * 8);
    }
    CP_COMMIT();
    // Stage chunks 0 and 1 into bufs 0 and 1 (groups 1 and 2)
    {
        int c0 = cl[0];
        attn_issue_chunk(g_k, g_v,
            (hb + (size_t)((n - 1 + (c0 >> 1)) * 128 + (c0 & 1) * 64)) * HD, 0, sbase);
        int c1 = cl[1];
        attn_issue_chunk(g_k, g_v,
            (hb + (size_t)((n - 1 + (c1 >> 1)) * 128 + (c1 & 1) * 64)) * HD, 1, sbase);
    }

    // Q fragments (wait leaves <=2 groups pending -> Q group complete)
    CP_WAIT(2);
    __syncthreads();
    unsigned qf[4][4];
    {
        const int row = warp * 16 + l15;
        const unsigned rbase = sbase + QOFF + row * 128;
        const unsigned xr = (row & 7) << 4;
#pragma unroll
        for (int kk = 0; kk < 4; kk++)
            LDSM4(qf[kk][0], qf[kk][1], qf[kk][2], qf[kk][3],
                  rbase + ((unsigned)(kk * 32 + hb16) ^ xr));
    }

    float oacc[8][4];
#pragma unroll
    for (int nd = 0; nd < 8; nd++)
#pragma unroll
        for (int e = 0; e < 4; e++) oacc[nd][e] = 0.f;
    float lr0 = 0.f, lr1 = 0.f;

    const int wq0 = warp * 16;
    const int qi0 = wq0 + g;

    int s = 0, s2 = 2;   // s = compute stage (i%3), s2 = stage for chunk i+2
    for (int i = 0; i < L; i++) {
        if (i + 1 < L) { CP_WAIT(1); }
        else           { CP_WAIT(0); }
        __syncthreads();   // protects buffer s2 (read at chunk i-1) for refill

        if (i + 2 < L) {
            int c = cl[i + 2];
            attn_issue_chunk(g_k, g_v,
                (hb + (size_t)((n - 1 + (c >> 1)) * 128 + (c & 1) * 64)) * HD,
                s2, sbase);
        }

        const unsigned kbs = sbase + KOFF(s);
        const unsigned vbs = sbase + VOFF(s);
        const int c  = cl[i];
        const int kb = c >> 1;
        const int jb = (c & 1) * 64;        // key offset within key block

        // Per-warp chunk skip: does [jb, jb+64) intersect this warp's band?
        const bool dowork =
            (kb == 1) || (kb == 0 ? (jb + 63 >= wq0) : (jb <= wq0 + 14));

        if (dowork) {
            // S = Q K^T : per warp [16 x 64], with per-16-key-block skip.
            float acc[8][4];
#pragma unroll
            for (int ni = 0; ni < 8; ni++)
#pragma unroll
                for (int e = 0; e < 4; e++) acc[ni][e] = 0.f;

#pragma unroll
            for (int jp = 0; jp < 4; jp++) {
                const int sblk = jb + jp * 16;
                // fully masked? kb0: sblk+15 < wq0 ; kb2: sblk > wq0 (16-multiples)
                const bool live = (kb == 1) ||
                    (kb == 0 ? (sblk + 15 >= wq0) : (sblk <= wq0));
                if (!live) continue;
                int row = jp * 16 + l15;
                unsigned rb2 = kbs + row * 128;
                unsigned xr = (row & 7) << 4;
#pragma unroll
                for (int kk = 0; kk < 4; kk++) {
                    unsigned r0, r1, r2, r3;
                    LDSM4(r0, r1, r2, r3, rb2 + ((unsigned)(kk * 32 + hb16) ^ xr));
                    MMA16816(acc[2 * jp],     qf[kk][0], qf[kk][1], qf[kk][2], qf[kk][3], r0, r2);
                    MMA16816(acc[2 * jp + 1], qf[kk][0], qf[kk][1], qf[kk][2], qf[kk][3], r1, r3);
                }
            }

            // mask + exp for ALL ni (zeroes masked lanes regardless of skips)
#pragma unroll
            for (int ni = 0; ni < 8; ni++) {
                const int j0 = jb + ni * 8 + tig * 2;   // key-in-block
                const int j1 = j0 + 1;
                bool v0, v1, v2, v3;
                if (kb == 1)      { v0 = v1 = v2 = v3 = true; }
                else if (kb == 0) { v0 = j0 >= qi0; v1 = j1 >= qi0;
                                    v2 = j0 >= qi0 + 8; v3 = j1 >= qi0 + 8; }
                else              { v0 = j0 < qi0; v1 = j1 < qi0;
                                    v2 = j0 < qi0 + 8; v3 = j1 < qi0 + 8; }
                float p0 = v0 ? __expf(acc[ni][0] * 0.125f) : 0.f;
                float p1 = v1 ? __expf(acc[ni][1] * 0.125f) : 0.f;
                float p2 = v2 ? __expf(acc[ni][2] * 0.125f) : 0.f;
                float p3 = v3 ? __expf(acc[ni][3] * 0.125f) : 0.f;
                lr0 += p0 + p1;
                lr1 += p2 + p3;
                acc[ni][0] = p0; acc[ni][1] = p1; acc[ni][2] = p2; acc[ni][3] = p3;
            }

            // O += P V with per-16-key-block skip (P fragments all-zero there)
#pragma unroll
            for (int jk = 0; jk < 4; jk++) {
                const int sblk = jb + jk * 16;
                const bool live = (kb == 1) ||
                    (kb == 0 ? (sblk + 15 >= wq0) : (sblk <= wq0));
                if (!live) continue;
                unsigned a0 = packh2(acc[2 * jk][0],     acc[2 * jk][1]);
                unsigned a1 = packh2(acc[2 * jk][2],     acc[2 * jk][3]);
                unsigned a2 = packh2(acc[2 * jk + 1][0], acc[2 * jk + 1][1]);
                unsigned a3 = packh2(acc[2 * jk + 1][2], acc[2 * jk + 1][3]);
                int row = jk * 16 + l15;
                unsigned rb2 = vbs + row * 128;
                unsigned xr = (row & 7) << 4;
#pragma unroll
                for (int np = 0; np < 4; np++) {
                    unsigned r0, r1, r2, r3;
                    LDSM4T(r0, r1, r2, r3, rb2 + ((unsigned)(np * 32 + hb16) ^ xr));
                    MMA16816(oacc[2 * np],     a0, a1, a2, a3, r0, r1);
                    MMA16816(oacc[2 * np + 1], a0, a1, a2, a3, r2, r3);
                }
            }
        }
        s  = (s  == 2) ? 0 : s  + 1;
        s2 = (s2 == 2) ? 0 : s2 + 1;
    }

    // finalize: intra-quad row sums, scale, store fp16
    lr0 += __shfl_xor_sync(0xffffffffu, lr0, 1);
    lr0 += __shfl_xor_sync(0xffffffffu, lr0, 2);
    lr1 += __shfl_xor_sync(0xffffffffu, lr1, 1);
    lr1 += __shfl_xor_sync(0xffffffffu, lr1, 2);
    const float inv0 = 1.f / lr0;
    const float inv1 = 1.f / lr1;

    const int row0 = n * 128 + warp * 16 + g;
    __half* ob0 = g_o + (((size_t)b * SEQ + row0) * NH + h) * HD;
    __half* ob1 = g_o + (((size_t)b * SEQ + row0 + 8) * NH + h) * HD;
#pragma unroll
    for (int nd = 0; nd < 8; nd++) {
        int d = nd * 8 + tig * 2;
        *(unsigned*)(ob0 + d) = packh2(oacc[nd][0] * inv0, oacc[nd][1] * inv0);
        *(unsigned*)(ob1 + d) = packh2(oacc[nd][2] * inv1, oacc[nd][3] * inv1);
    }
}

// ---------------------------------------------------------------------------
extern "C" void kernel_launch(void* const* d_in, const int* in_sizes, int n_in,
                              void* d_out, int out_size)
{
    const float* inputs_q  = (const float*)d_in[0];
    const float* inputs_kv = (const float*)d_in[1];
    const float* Wq = (const float*)d_in[2];
    const float* bq = (const float*)d_in[3];
    const float* Wk = (const float*)d_in[4];
    const float* bk = (const float*)d_in[5];
    const float* Wv = (const float*)d_in[6];
    const float* bv = (const float*)d_in[7];
    const float* Wo = (const float*)d_in[8];
    const float* bo = (const float*)d_in[9];
    float* out = (float*)d_out;

    // Idempotent host-side calls, executed every invocation (no static state).
    cudaFuncSetAttribute(qkv_kernel,   cudaFuncAttributeMaxDynamicSharedMemorySize, GEMM_SMEM);
    cudaFuncSetAttribute(oproj_kernel, cudaFuncAttributeMaxDynamicSharedMemorySize, GEMM_SMEM);
    cudaFuncSetAttribute(attn_kernel,  cudaFuncAttributeMaxDynamicSharedMemorySize, ATTN_SMEM);

    pre_kernel<<<2048, 256>>>((const float4*)inputs_q, (const float4*)inputs_kv,
                              Wq, Wk, Wv, Wo);

    dim3 gq(FD / 64, MROWS / 128, 3);
    qkv_kernel<<<gq, 128, GEMM_SMEM>>>(bq, bk, bv);

    dim3 ga(NB, NH, BSZ);
    attn_kernel<<<ga, 256, ATTN_SMEM>>>();

    dim3 go(FD / 64, MROWS / 128, 1);
    oproj_kernel<<<go, 128, GEMM_SMEM>>>(bo, out);
}

// round 17
// speedup vs baseline: 1.0501x; 1.0281x over previous
#include <cuda_runtime.h>
#include <cuda_fp16.h>
#include <cstdint>

// Problem constants
#define BSZ 2
#define SEQ 8192
#define FD  512
#define NH  8
#define HD  64
#define NB  64          // SEQ / 128
#define MROWS (BSZ*SEQ) // 16384
#define NTK  8          // k-tiles of 64 over FD

// Scratch (allocation-free rule -> __device__ globals). fp16 everywhere.
__device__ __half g_aq [(size_t)MROWS*FD];     // inputs_q  fp16
__device__ __half g_akv[(size_t)MROWS*FD];     // inputs_kv fp16
__device__ __half g_wq [(size_t)FD*FD];        // W transposed [n][k] fp16
__device__ __half g_wk [(size_t)FD*FD];
__device__ __half g_wv [(size_t)FD*FD];
__device__ __half g_wo [(size_t)FD*FD];
__device__ __half g_q[(size_t)BSZ*NH*SEQ*HD];  // [B,H,S,D]
__device__ __half g_k[(size_t)BSZ*NH*SEQ*HD];
__device__ __half g_v[(size_t)BSZ*NH*SEQ*HD];
__device__ __half g_o[(size_t)BSZ*SEQ*NH*HD];  // [B,S,H,D]

__device__ __forceinline__ unsigned smaddr(const void* p) {
    return (unsigned)__cvta_generic_to_shared(p);
}
__device__ __forceinline__ unsigned packh2(float lo, float hi) {
    unsigned r;
    asm("cvt.rn.f16x2.f32 %0, %1, %2;" : "=r"(r) : "f"(hi), "f"(lo));
    return r;
}
__device__ __forceinline__ float ex2(float x) {
    float r;
    asm("ex2.approx.f32 %0, %1;" : "=f"(r) : "f"(x));
    return r;
}
#define CP16(dst, src) asm volatile("cp.async.cg.shared.global [%0], [%1], 16;\n" :: "r"(dst), "l"(src))
#define CP_COMMIT()    asm volatile("cp.async.commit_group;\n")
#define CP_WAIT(n)     asm volatile("cp.async.wait_group %0;\n" :: "n"(n))

#define LDSM4(r0,r1,r2,r3,a) \
    asm volatile("ldmatrix.sync.aligned.m8n8.x4.shared.b16 {%0,%1,%2,%3}, [%4];" \
                 : "=r"(r0), "=r"(r1), "=r"(r2), "=r"(r3) : "r"(a))
#define LDSM4T(r0,r1,r2,r3,a) \
    asm volatile("ldmatrix.sync.aligned.m8n8.x4.trans.shared.b16 {%0,%1,%2,%3}, [%4];" \
                 : "=r"(r0), "=r"(r1), "=r"(r2), "=r"(r3) : "r"(a))
#define MMA16816(c, a0,a1,a2,a3, b0,b1) \
    asm volatile("mma.sync.aligned.m16n8k16.row.col.f32.f16.f16.f32 " \
                 "{%0,%1,%2,%3}, {%4,%5,%6,%7}, {%8,%9}, {%0,%1,%2,%3};" \
                 : "+f"((c)[0]), "+f"((c)[1]), "+f"((c)[2]), "+f"((c)[3]) \
                 : "r"(a0), "r"(a1), "r"(a2), "r"(a3), "r"(b0), "r"(b1))
// fp16-accumulate variant: C/D = 2 regs (4 halves). Layout matches f32 C
// positionally: c0 = {col2t, col2t+1} @ row g ; c1 = same @ row g+8.
#define MMA16816H(c, a0,a1,a2,a3, b0,b1) \
    asm volatile("mma.sync.aligned.m16n8k16.row.col.f16.f16.f16.f16 " \
                 "{%0,%1}, {%2,%3,%4,%5}, {%6,%7}, {%0,%1};" \
                 : "+r"((c)[0]), "+r"((c)[1]) \
                 : "r"(a0), "r"(a1), "r"(a2), "r"(a3), "r"(b0), "r"(b1))

// ---------------------------------------------------------------------------
// Kernel 0: fused preamble. blocks [0,1024): activations fp32->fp16.
// blocks [1024,2048): weight transpose+convert dst[n][k] = fp16(src[k][n]).
// ---------------------------------------------------------------------------
#define SEG_A 2097152u             // MROWS*FD/4
__global__ void pre_kernel(
    const float4* __restrict__ q, const float4* __restrict__ kv,
    const float* __restrict__ wq, const float* __restrict__ wk,
    const float* __restrict__ wv, const float* __restrict__ wo)
{
    __shared__ float t[32][33];
    const int tid = threadIdx.x;
    if (blockIdx.x < 1024) {
        for (unsigned i = blockIdx.x * 256 + tid; i < 2 * SEG_A; i += 1024 * 256) {
            const float4* src = (i < SEG_A) ? q : kv;
            uint2* dst = (i < SEG_A) ? (uint2*)g_aq : (uint2*)g_akv;
            unsigned off = (i < SEG_A) ? i : i - SEG_A;
            float4 v = src[off];
            dst[off] = make_uint2(packh2(v.x, v.y), packh2(v.z, v.w));
        }
    } else {
        const int bid = blockIdx.x - 1024;      // 0..1023
        const int z = bid >> 8;                 // weight index
        const int tt = bid & 255;
        const float* src = (z == 0) ? wq : (z == 1 ? wk : (z == 2 ? wv : wo));
        __half* dst      = (z == 0) ? g_wq : (z == 1 ? g_wk : (z == 2 ? g_wv : g_wo));
        const int bk = (tt & 15) * 32;
        const int bn = (tt >> 4) * 32;
        const int tx = tid & 31;
        const int ty = tid >> 5;                // 0..7
#pragma unroll
        for (int i = 0; i < 4; i++) {
            int k = ty + i * 8;
            t[k][tx] = src[(size_t)(bk + k) * FD + bn + tx];
        }
        __syncthreads();
#pragma unroll
        for (int i = 0; i < 4; i++) {
            int nn = ty + i * 8;
            dst[(size_t)(bn + nn) * FD + bk + tx] = __float2half_rn(t[tx][nn]);
        }
    }
}

// ---------------------------------------------------------------------------
// fp16 GEMM body (round-14, unchanged): C 128x64 tile, BK=64, 128 threads
// (4 warps, 32x64 tiles). 2-stage cp.async, 48KB/CTA -> 4 CTAs/SM.
// ---------------------------------------------------------------------------
#define G2ST 24576u
#define GAOF(s) ((s) * G2ST)
#define GBOF(s) ((s) * G2ST + 16384u)
#define GEMM_SMEM 49152

__device__ __forceinline__ void gemm_issue16(
    const __half* __restrict__ A, const __half* __restrict__ Bt,
    int m0, int n0, int kt, int s, unsigned sbase)
{
    const int tid = threadIdx.x;
    const unsigned ab = sbase + GAOF(s);
    const unsigned bb = sbase + GBOF(s);
#pragma unroll
    for (int i = 0; i < 8; i++) {          // A: 1024 units (128 rows x 8)
        int u = i * 128 + tid;
        int row = u >> 3, un = u & 7;
        unsigned sw = (unsigned)(row * 128) + ((un * 16) ^ ((row & 7) << 4));
        CP16(ab + sw, A + (size_t)(m0 + row) * FD + kt * 64 + un * 8);
    }
#pragma unroll
    for (int i = 0; i < 4; i++) {          // B: 512 units (64 rows x 8)
        int u = i * 128 + tid;
        int row = u >> 3, un = u & 7;
        unsigned sw = (unsigned)(row * 128) + ((un * 16) ^ ((row & 7) << 4));
        CP16(bb + sw, Bt + (size_t)(n0 + row) * FD + kt * 64 + un * 8);
    }
    CP_COMMIT();
}

__device__ __forceinline__ void gemm16_body(
    const __half* __restrict__ A, const __half* __restrict__ Bt,
    int m0, int n0, float acc[2][8][4], char* smem)
{
    const int lane = threadIdx.x & 31;
    const int warp = threadIdx.x >> 5;     // 0..3
    const int wm = warp * 32;
    const unsigned sbase = smaddr(smem);
    const int l15 = lane & 15;
    const int hb16 = (lane & 16) ? 16 : 0;

    gemm_issue16(A, Bt, m0, n0, 0, 0, sbase);
    gemm_issue16(A, Bt, m0, n0, 1, 1, sbase);

    for (int kt = 0; kt < NTK; kt++) {
        const int buf = kt & 1;
        if (kt + 2 < NTK) { CP_WAIT(1); }
        else              { CP_WAIT(0); }
        __syncthreads();

        const unsigned ab = sbase + GAOF(buf);
        const unsigned bb = sbase + GBOF(buf);
#pragma unroll
        for (int kk = 0; kk < 4; kk++) {
            const int bcol = kk * 32 + hb16;
            unsigned af[2][4];
#pragma unroll
            for (int mi = 0; mi < 2; mi++) {
                int row = wm + mi * 16 + l15;
                unsigned ad = ab + row * 128 + (bcol ^ ((row & 7) << 4));
                LDSM4(af[mi][0], af[mi][1], af[mi][2], af[mi][3], ad);
            }
#pragma unroll
            for (int np = 0; np < 4; np++) {
                int row = np * 16 + l15;
                unsigned bd = bb + row * 128 + (bcol ^ ((row & 7) << 4));
                unsigned r0, r1, r2, r3;
                LDSM4(r0, r1, r2, r3, bd);
#pragma unroll
                for (int mi = 0; mi < 2; mi++) {
                    MMA16816(acc[mi][2 * np],     af[mi][0], af[mi][1], af[mi][2], af[mi][3], r0, r2);
                    MMA16816(acc[mi][2 * np + 1], af[mi][0], af[mi][1], af[mi][2], af[mi][3], r1, r3);
                }
            }
        }
        __syncthreads();
        if (kt + 2 < NTK)
            gemm_issue16(A, Bt, m0, n0, kt + 2, buf, sbase);
    }
}

// ---------------------------------------------------------------------------
// Kernel 1: QKV projection. grid = (8, 128, 3). 128 threads, 4 CTAs/SM.
// ---------------------------------------------------------------------------
__global__ void __launch_bounds__(128, 4) qkv_kernel(
    const float* __restrict__ bq, const float* __restrict__ bk,
    const float* __restrict__ bv)
{
    extern __shared__ char smem[];
    const int z = blockIdx.z;
    const __half* A  = (z == 0) ? g_aq : g_akv;
    const __half* Bt = (z == 0) ? g_wq : (z == 1 ? g_wk : g_wv);
    const float* bias = (z == 0) ? bq : (z == 1 ? bk : bv);
    __half* O        = (z == 0) ? g_q : (z == 1 ? g_k : g_v);

    const int n0 = blockIdx.x * 64;
    const int m0 = blockIdx.y * 128;

    float acc[2][8][4];
#pragma unroll
    for (int mi = 0; mi < 2; mi++)
#pragma unroll
        for (int ni = 0; ni < 8; ni++)
#pragma unroll
            for (int j = 0; j < 4; j++) acc[mi][ni][j] = 0.f;

    gemm16_body(A, Bt, m0, n0, acc, smem);

    const int lane = threadIdx.x & 31;
    const int warp = threadIdx.x >> 5;
    const int wm = warp * 32;
    const int g   = lane >> 2;
    const int tig = lane & 3;
    const int h   = n0 >> 6;                   // fixed per CTA

#pragma unroll
    for (int mi = 0; mi < 2; mi++) {
#pragma unroll
        for (int ni = 0; ni < 8; ni++) {
            int col = n0 + ni * 8 + tig * 2;
            int db = col & 63;
            float2 bb = *(const float2*)(bias + col);
            int row0 = m0 + wm + mi * 16 + g;
            int b = row0 >> 13;
            int s0 = row0 & (SEQ - 1);
            __half* base = O + ((size_t)(b * NH + h)) * (SEQ * HD) + db;
            *(unsigned*)(base + (size_t)s0 * HD) =
                packh2(acc[mi][ni][0] + bb.x, acc[mi][ni][1] + bb.y);
            *(unsigned*)(base + (size_t)(s0 + 8) * HD) =
                packh2(acc[mi][ni][2] + bb.x, acc[mi][ni][3] + bb.y);
        }
    }
}

// ---------------------------------------------------------------------------
// Kernel 3: output projection. grid = (8, 128). 128 threads, 4 CTAs/SM.
// ---------------------------------------------------------------------------
__global__ void __launch_bounds__(128, 4) oproj_kernel(
    const float* __restrict__ bo, float* __restrict__ Out)
{
    extern __shared__ char smem[];
    const int n0 = blockIdx.x * 64;
    const int m0 = blockIdx.y * 128;

    float acc[2][8][4];
#pragma unroll
    for (int mi = 0; mi < 2; mi++)
#pragma unroll
        for (int ni = 0; ni < 8; ni++)
#pragma unroll
            for (int j = 0; j < 4; j++) acc[mi][ni][j] = 0.f;

    gemm16_body(g_o, g_wo, m0, n0, acc, smem);

    const int lane = threadIdx.x & 31;
    const int warp = threadIdx.x >> 5;
    const int wm = warp * 32;
    const int g   = lane >> 2;
    const int tig = lane & 3;

#pragma unroll
    for (int mi = 0; mi < 2; mi++) {
#pragma unroll
        for (int ni = 0; ni < 8; ni++) {
            int col = n0 + ni * 8 + tig * 2;
            float2 bb = *(const float2*)(bo + col);
            int row0 = m0 + wm + mi * 16 + g;
            *(float2*)(Out + (size_t)row0 * FD + col) =
                make_float2(acc[mi][ni][0] + bb.x, acc[mi][ni][1] + bb.y);
            *(float2*)(Out + (size_t)(row0 + 8) * FD + col) =
                make_float2(acc[mi][ni][2] + bb.x, acc[mi][ni][3] + bb.y);
        }
    }
}

// ---------------------------------------------------------------------------
// Kernel 2: banded local attention. grid = (NB, NH, BSZ). 256 threads.
// 3-buffer / 2-ahead K,V pipeline, ONE __syncthreads per chunk.
// Fragment-level band skip (round 14). This round:
//  - QK uses fp16 accumulators (MMA16816H, 2-reg C).
//  - exp folded to a single ex2.approx with pre-multiplied constant.
//  - P packed to fp16 pairs once in the exp pass (PV pack hoisted).
// PV keeps fp32 accumulation (long chain -> fp16 would risk 1e-3).
// Smem: Q 16KB @0; 3 stages x (K 8KB + V 8KB) @16384. Total 64KB.
// ---------------------------------------------------------------------------
#define QOFF 0u
#define KOFF(s) (16384u + (s) * 16384u)
#define VOFF(s) (16384u + (s) * 16384u + 8192u)
#define ATTN_SMEM 65536
#define EXPC 0.18033688f   // 0.125 * log2(e)

__device__ __forceinline__ void attn_issue_chunk(
    const __half* gk, const __half* gv, size_t rb, int s, unsigned sbase)
{
    const int tid = threadIdx.x;
#pragma unroll
    for (int i = 0; i < 2; i++) {
        int u = i * 256 + tid;          // 512 units: 64 rows x 8
        int row = u >> 3, un = u & 7;
        unsigned sw = (unsigned)(row * 128) + ((un * 16) ^ ((row & 7) << 4));
        CP16(sbase + KOFF(s) + sw, gk + rb + (size_t)row * HD + un * 8);
        CP16(sbase + VOFF(s) + sw, gv + rb + (size_t)row * HD + un * 8);
    }
    CP_COMMIT();
}

__global__ void __launch_bounds__(256, 2) attn_kernel()
{
    extern __shared__ char smem[];
    const unsigned sbase = smaddr(smem);

    const int n = blockIdx.x, h = blockIdx.y, b = blockIdx.z;
    const int tid  = threadIdx.x;
    const int lane = tid & 31;
    const int warp = tid >> 5;
    const int g    = lane >> 2;
    const int tig  = lane & 3;
    const int l15  = lane & 15;
    const int hb16 = (lane & 16) ? 16 : 0;
    const size_t hb = ((size_t)(b * NH + h)) * SEQ;

    // Chunk list (kb*2+ch); only out-of-range key blocks are dropped.
    int cl[6]; int L = 0;
#pragma unroll
    for (int kb = 0; kb < 3; kb++) {
        int kn = n - 1 + kb;
        if (kn < 0 || kn >= NB) continue;
#pragma unroll
        for (int ch = 0; ch < 2; ch++) cl[L++] = kb * 2 + ch;
    }

    // Stage Q [128 x 64halves] (group 0)
#pragma unroll
    for (int i = 0; i < 4; i++) {
        int u = i * 256 + tid;              // 1024 units
        int row = u >> 3, un = u & 7;
        unsigned sw = (unsigned)(row * 128) + ((un * 16) ^ ((row & 7) << 4));
        CP16(sbase + QOFF + sw, g_q + (hb + (size_t)(n * 128 + row)) * HD + un * 8);
    }
    CP_COMMIT();
    // Stage chunks 0 and 1 into bufs 0 and 1 (groups 1 and 2)
    {
        int c0 = cl[0];
        attn_issue_chunk(g_k, g_v,
            (hb + (size_t)((n - 1 + (c0 >> 1)) * 128 + (c0 & 1) * 64)) * HD, 0, sbase);
        int c1 = cl[1];
        attn_issue_chunk(g_k, g_v,
            (hb + (size_t)((n - 1 + (c1 >> 1)) * 128 + (c1 & 1) * 64)) * HD, 1, sbase);
    }

    // Q fragments (wait leaves <=2 groups pending -> Q group complete)
    CP_WAIT(2);
    __syncthreads();
    unsigned qf[4][4];
    {
        const int row = warp * 16 + l15;
        const unsigned rbase = sbase + QOFF + row * 128;
        const unsigned xr = (row & 7) << 4;
#pragma unroll
        for (int kk = 0; kk < 4; kk++)
            LDSM4(qf[kk][0], qf[kk][1], qf[kk][2], qf[kk][3],
                  rbase + ((unsigned)(kk * 32 + hb16) ^ xr));
    }

    float oacc[8][4];
#pragma unroll
    for (int nd = 0; nd < 8; nd++)
#pragma unroll
        for (int e = 0; e < 4; e++) oacc[nd][e] = 0.f;
    float lr0 = 0.f, lr1 = 0.f;

    const int wq0 = warp * 16;
    const int qi0 = wq0 + g;

    int s = 0, s2 = 2;   // s = compute stage (i%3), s2 = stage for chunk i+2
    for (int i = 0; i < L; i++) {
        if (i + 1 < L) { CP_WAIT(1); }
        else           { CP_WAIT(0); }
        __syncthreads();   // protects buffer s2 (read at chunk i-1) for refill

        if (i + 2 < L) {
            int c = cl[i + 2];
            attn_issue_chunk(g_k, g_v,
                (hb + (size_t)((n - 1 + (c >> 1)) * 128 + (c & 1) * 64)) * HD,
                s2, sbase);
        }

        const unsigned kbs = sbase + KOFF(s);
        const unsigned vbs = sbase + VOFF(s);
        const int c  = cl[i];
        const int kb = c >> 1;
        const int jb = (c & 1) * 64;        // key offset within key block

        // Per-warp chunk skip: does [jb, jb+64) intersect this warp's band?
        const bool dowork =
            (kb == 1) || (kb == 0 ? (jb + 63 >= wq0) : (jb <= wq0 + 14));

        if (dowork) {
            // S = Q K^T : fp16 accumulators, per-16-key-block skip.
            unsigned acch[8][2];
#pragma unroll
            for (int ni = 0; ni < 8; ni++) { acch[ni][0] = 0u; acch[ni][1] = 0u; }

#pragma unroll
            for (int jp = 0; jp < 4; jp++) {
                const int sblk = jb + jp * 16;
                const bool live = (kb == 1) ||
                    (kb == 0 ? (sblk + 15 >= wq0) : (sblk <= wq0));
                if (!live) continue;
                int row = jp * 16 + l15;
                unsigned rb2 = kbs + row * 128;
                unsigned xr = (row & 7) << 4;
#pragma unroll
                for (int kk = 0; kk < 4; kk++) {
                    unsigned r0, r1, r2, r3;
                    LDSM4(r0, r1, r2, r3, rb2 + ((unsigned)(kk * 32 + hb16) ^ xr));
                    MMA16816H(acch[2 * jp],     qf[kk][0], qf[kk][1], qf[kk][2], qf[kk][3], r0, r2);
                    MMA16816H(acch[2 * jp + 1], qf[kk][0], qf[kk][1], qf[kk][2], qf[kk][3], r1, r3);
                }
            }

            // mask + ex2; produce packed fp16 P fragments + fp32 row sums.
            unsigned pf[8][2];
#pragma unroll
            for (int ni = 0; ni < 8; ni++) {
                const int j0 = jb + ni * 8 + tig * 2;   // key-in-block
                const int j1 = j0 + 1;
                bool v0, v1, v2, v3;
                if (kb == 1)      { v0 = v1 = v2 = v3 = true; }
                else if (kb == 0) { v0 = j0 >= qi0; v1 = j1 >= qi0;
                                    v2 = j0 >= qi0 + 8; v3 = j1 >= qi0 + 8; }
                else              { v0 = j0 < qi0; v1 = j1 < qi0;
                                    v2 = j0 < qi0 + 8; v3 = j1 < qi0 + 8; }
                float2 e01 = __half22float2(*(__half2*)&acch[ni][0]);
                float2 e23 = __half22float2(*(__half2*)&acch[ni][1]);
                float p0 = v0 ? ex2(e01.x * EXPC) : 0.f;
                float p1 = v1 ? ex2(e01.y * EXPC) : 0.f;
                float p2 = v2 ? ex2(e23.x * EXPC) : 0.f;
                float p3 = v3 ? ex2(e23.y * EXPC) : 0.f;
                lr0 += p0 + p1;
                lr1 += p2 + p3;
                pf[ni][0] = packh2(p0, p1);
                pf[ni][1] = packh2(p2, p3);
            }

            // O += P V (fp32 acc); per-16-key-block skip; V via ldmatrix.trans
#pragma unroll
            for (int jk = 0; jk < 4; jk++) {
                const int sblk = jb + jk * 16;
                const bool live = (kb == 1) ||
                    (kb == 0 ? (sblk + 15 >= wq0) : (sblk <= wq0));
                if (!live) continue;
                unsigned a0 = pf[2 * jk][0];
                unsigned a1 = pf[2 * jk][1];
                unsigned a2 = pf[2 * jk + 1][0];
                unsigned a3 = pf[2 * jk + 1][1];
                int row = jk * 16 + l15;
                unsigned rb2 = vbs + row * 128;
                unsigned xr = (row & 7) << 4;
#pragma unroll
                for (int np = 0; np < 4; np++) {
                    unsigned r0, r1, r2, r3;
                    LDSM4T(r0, r1, r2, r3, rb2 + ((unsigned)(np * 32 + hb16) ^ xr));
                    MMA16816(oacc[2 * np],     a0, a1, a2, a3, r0, r1);
                    MMA16816(oacc[2 * np + 1], a0, a1, a2, a3, r2, r3);
                }
            }
        }
        s  = (s  == 2) ? 0 : s  + 1;
        s2 = (s2 == 2) ? 0 : s2 + 1;
    }

    // finalize: intra-quad row sums, scale, store fp16
    lr0 += __shfl_xor_sync(0xffffffffu, lr0, 1);
    lr0 += __shfl_xor_sync(0xffffffffu, lr0, 2);
    lr1 += __shfl_xor_sync(0xffffffffu, lr1, 1);
    lr1 += __shfl_xor_sync(0xffffffffu, lr1, 2);
    const float inv0 = 1.f / lr0;
    const float inv1 = 1.f / lr1;

    const int row0 = n * 128 + warp * 16 + g;
    __half* ob0 = g_o + (((size_t)b * SEQ + row0) * NH + h) * HD;
    __half* ob1 = g_o + (((size_t)b * SEQ + row0 + 8) * NH + h) * HD;
#pragma unroll
    for (int nd = 0; nd < 8; nd++) {
        int d = nd * 8 + tig * 2;
        *(unsigned*)(ob0 + d) = packh2(oacc[nd][0] * inv0, oacc[nd][1] * inv0);
        *(unsigned*)(ob1 + d) = packh2(oacc[nd][2] * inv1, oacc[nd][3] * inv1);
    }
}

// ---------------------------------------------------------------------------
extern "C" void kernel_launch(void* const* d_in, const int* in_sizes, int n_in,
                              void* d_out, int out_size)
{
    const float* inputs_q  = (const float*)d_in[0];
    const float* inputs_kv = (const float*)d_in[1];
    const float* Wq = (const float*)d_in[2];
    const float* bq = (const float*)d_in[3];
    const float* Wk = (const float*)d_in[4];
    const float* bk = (const float*)d_in[5];
    const float* Wv = (const float*)d_in[6];
    const float* bv = (const float*)d_in[7];
    const float* Wo = (const float*)d_in[8];
    const float* bo = (const float*)d_in[9];
    float* out = (float*)d_out;

    // Idempotent host-side calls, executed every invocation (no static state).
    cudaFuncSetAttribute(qkv_kernel,   cudaFuncAttributeMaxDynamicSharedMemorySize, GEMM_SMEM);
    cudaFuncSetAttribute(oproj_kernel, cudaFuncAttributeMaxDynamicSharedMemorySize, GEMM_SMEM);
    cudaFuncSetAttribute(attn_kernel,  cudaFuncAttributeMaxDynamicSharedMemorySize, ATTN_SMEM);

    pre_kernel<<<2048, 256>>>((const float4*)inputs_q, (const float4*)inputs_kv,
                              Wq, Wk, Wv, Wo);

    dim3 gq(FD / 64, MROWS / 128, 3);
    qkv_kernel<<<gq, 128, GEMM_SMEM>>>(bq, bk, bv);

    dim3 ga(NB, NH, BSZ);
    attn_kernel<<<ga, 256, ATTN_SMEM>>>();

    dim3 go(FD / 64, MROWS / 128, 1);
    oproj_kernel<<<go, 128, GEMM_SMEM>>>(bo, out);
}